// round 1
// baseline (speedup 1.0000x reference)
#include <cuda_runtime.h>

#define NLAYERS 10
#define HID     100
#define HPAD    104
#define BATCH   512
#define TSTEPS  512
#define NCHUNK  16
#define CHUNKB  32
#define RING_D  4
#define NTHREADS 256
#define NWARPS   8
#define JPW      13   // output units per warp (8*13 = 104 >= 100)

// ---- shared memory layout (in floats) ----
#define OFF_WI   0
#define OFF_WH   (HPAD*HID)
#define OFF_BIAS (2*HPAD*HID)
#define OFF_AUX  (OFF_BIAS + HPAD)
#define OFF_H    (OFF_AUX + HPAD)
#define OFF_INP  (OFF_H + CHUNKB*HID)
#define OFF_RED  (OFF_INP + CHUNKB*HID)
#define OFF_SC   (OFF_RED + NWARPS*32)
#define SMEM_FLOATS (OFF_SC + 4)

// ---- global scratch: activation ring + flags (no allocation allowed) ----
#define NPAIRS ((NLAYERS-1)*NCHUNK)
__device__ float    g_ring[(size_t)NPAIRS * RING_D * CHUNKB * HID];
__device__ unsigned g_prod[NPAIRS];
__device__ unsigned g_cons[NPAIRS];

__device__ __forceinline__ unsigned ld_acq(const unsigned* p) {
    unsigned v;
    asm volatile("ld.acquire.gpu.global.u32 %0, [%1];" : "=r"(v) : "l"(p) : "memory");
    return v;
}
__device__ __forceinline__ void st_rel(unsigned* p, unsigned v) {
    asm volatile("st.release.gpu.global.u32 [%0], %1;" :: "l"(p), "r"(v) : "memory");
}
__device__ __forceinline__ unsigned long long ffma2(unsigned long long a,
                                                    unsigned long long b,
                                                    unsigned long long c) {
    unsigned long long d;
    asm("fma.rn.f32x2 %0, %1, %2, %3;" : "=l"(d) : "l"(a), "l"(b), "l"(c));
    return d;
}
__device__ __forceinline__ unsigned long long pack2(float lo, float hi) {
    unsigned long long r;
    asm("mov.b64 %0, {%1, %2};" : "=l"(r) : "f"(lo), "f"(hi));
    return r;
}
__device__ __forceinline__ float hsum2(unsigned long long v) {
    float a, b;
    asm("mov.b64 {%0, %1}, %2;" : "=f"(a), "=f"(b) : "l"(v));
    return a + b;
}

__global__ void rnn_reset_kernel() {
    int i = threadIdx.x;
    if (i < NPAIRS) { g_prod[i] = 0u; g_cons[i] = 0u; }
}

__global__ __launch_bounds__(NTHREADS, 2)
void rnn_kernel(const float* __restrict__ x,      // [B, T, 1]
                const float* __restrict__ h0,     // [L, B, H]
                const float* __restrict__ Wi0,    // [H, 1]
                const float* __restrict__ Wih,    // [L-1, H, H]
                const float* __restrict__ Whh,    // [L, H, H]
                const float* __restrict__ bih,    // [L, H]
                const float* __restrict__ bhh,    // [L, H]
                const float* __restrict__ Wout,   // [1, H]
                const float* __restrict__ bout,   // [1]
                float* __restrict__ out)          // [B*T] outs ++ [L*B*H] h_final
{
    extern __shared__ float sm[];
    float* sWi   = sm + OFF_WI;
    float* sWh   = sm + OFF_WH;
    float* sBias = sm + OFF_BIAS;
    float* sAux  = sm + OFF_AUX;   // layer 0: Wi0; layer 9: Wout
    float* sH    = sm + OFF_H;
    float* sInp  = sm + OFF_INP;
    float* sRed  = sm + OFF_RED;
    float* sSC   = sm + OFF_SC;

    const int tid   = threadIdx.x;
    const int warp  = tid >> 5;
    const int lane  = tid & 31;
    const int layer = blockIdx.x / NCHUNK;
    const int chunk = blockIdx.x % NCHUNK;
    const int b0    = chunk * CHUNKB;
    const int jbase = warp * JPW;

    // ---------------- init weights / biases / state into smem ----------------
    {
        const float* gWi = Wih + (size_t)(layer - 1) * HID * HID; // valid only layer>0
        const float* gWh = Whh + (size_t)layer * HID * HID;
        for (int idx = tid; idx < HPAD * HID; idx += NTHREADS) {
            int j = idx / HID;
            sWi[idx] = (layer > 0 && j < HID) ? gWi[idx] : 0.f;
            sWh[idx] = (j < HID) ? gWh[idx] : 0.f;
        }
        for (int idx = tid; idx < HPAD; idx += NTHREADS) {
            sBias[idx] = (idx < HID) ? (bih[layer * HID + idx] + bhh[layer * HID + idx]) : 0.f;
            float aux = 0.f;
            if (idx < HID) {
                if (layer == 0) aux = Wi0[idx];
                else if (layer == NLAYERS - 1) aux = Wout[idx];
            }
            sAux[idx] = aux;
        }
        const float* gh = h0 + (size_t)layer * BATCH * HID + (size_t)b0 * HID;
        for (int idx = tid; idx < CHUNKB * HID; idx += NTHREADS) sH[idx] = gh[idx];
        if (tid == 0) sSC[0] = bout[0];
    }
    __syncthreads();

    const int pc_in  = (layer - 1) * NCHUNK + chunk;  // consumer pair (layer>0)
    const int pc_out = layer * NCHUNK + chunk;        // producer pair (layer<9)
    float* ring_in  = g_ring + (size_t)pc_in  * RING_D * CHUNKB * HID;
    float* ring_out = g_ring + (size_t)pc_out * RING_D * CHUNKB * HID;

    const float* hrow = sH + lane * HID;
    const float* irow = sInp + lane * HID;

    for (int t = 0; t < TSTEPS; t++) {
        // -------- acquire input --------
        float xv = 0.f;
        if (layer == 0) {
            xv = x[(size_t)(b0 + lane) * TSTEPS + t];
        } else {
            if (tid == 0) {
                while (ld_acq(&g_prod[pc_in]) < (unsigned)(t + 1)) {}
            }
            __syncthreads();
            const float4* slot = (const float4*)(ring_in + (size_t)(t & (RING_D - 1)) * CHUNKB * HID);
            float4* dst = (float4*)sInp;
            for (int i = tid; i < CHUNKB * HID / 4; i += NTHREADS) dst[i] = slot[i];
            __syncthreads();
            if (tid == 0) st_rel(&g_cons[pc_in], (unsigned)(t + 1));
        }

        // -------- compute h_new = tanh(W_ih*inp + W_hh*h + b) --------
        unsigned long long acc[JPW];
#pragma unroll
        for (int i = 0; i < JPW; i++) {
            float b = sBias[jbase + i];
            if (layer == 0) b += xv * sAux[jbase + i];
            acc[i] = pack2(b, 0.f);
        }

        if (layer == 0) {
            for (int k = 0; k < HID; k += 4) {
                ulonglong2 h2 = *(const ulonglong2*)(hrow + k);
#pragma unroll
                for (int i = 0; i < JPW; i++) {
                    ulonglong2 wh = *(const ulonglong2*)(sWh + (jbase + i) * HID + k);
                    acc[i] = ffma2(h2.x, wh.x, acc[i]);
                    acc[i] = ffma2(h2.y, wh.y, acc[i]);
                }
            }
        } else {
            for (int k = 0; k < HID; k += 4) {
                ulonglong2 h2  = *(const ulonglong2*)(hrow + k);
                ulonglong2 in2 = *(const ulonglong2*)(irow + k);
#pragma unroll
                for (int i = 0; i < JPW; i++) {
                    ulonglong2 wh = *(const ulonglong2*)(sWh + (jbase + i) * HID + k);
                    ulonglong2 wi = *(const ulonglong2*)(sWi + (jbase + i) * HID + k);
                    acc[i] = ffma2(h2.x,  wh.x, acc[i]);
                    acc[i] = ffma2(h2.y,  wh.y, acc[i]);
                    acc[i] = ffma2(in2.x, wi.x, acc[i]);
                    acc[i] = ffma2(in2.y, wi.y, acc[i]);
                }
            }
        }

        float hn[JPW];
#pragma unroll
        for (int i = 0; i < JPW; i++) hn[i] = tanhf(hsum2(acc[i]));

        __syncthreads();  // all reads of sH done before overwrite
#pragma unroll
        for (int i = 0; i < JPW; i++) {
            int j = jbase + i;
            if (j < HID) sH[lane * HID + j] = hn[i];
        }

        // -------- publish / output --------
        if (layer < NLAYERS - 1) {
            if (tid == 0 && t >= RING_D) {
                unsigned need = (unsigned)(t + 1 - RING_D);
                while (ld_acq(&g_cons[pc_out]) < need) {}
            }
            __syncthreads();  // backpressure known + sH writes visible
            float* slot = ring_out + (size_t)(t & (RING_D - 1)) * CHUNKB * HID;
#pragma unroll
            for (int i = 0; i < JPW; i++) {
                int j = jbase + i;
                if (j < HID) slot[lane * HID + j] = hn[i];
            }
            __threadfence();
            __syncthreads();
            if (tid == 0) st_rel(&g_prod[pc_out], (unsigned)(t + 1));
        } else {
            // layer 9: out[b][t] = dot(h_new, Wout) + b_out
            float part = 0.f;
#pragma unroll
            for (int i = 0; i < JPW; i++) {
                int j = jbase + i;
                if (j < HID) part += hn[i] * sAux[j];
            }
            sRed[warp * 32 + lane] = part;
            __syncthreads();
            if (warp == 0) {
                float s = sSC[0];
#pragma unroll
                for (int w = 0; w < NWARPS; w++) s += sRed[w * 32 + lane];
                out[(size_t)(b0 + lane) * TSTEPS + t] = s;
            }
            __syncthreads();
        }
    }

    // -------- final hidden state --------
    __syncthreads();
    float* hf = out + (size_t)BATCH * TSTEPS + (size_t)layer * BATCH * HID + (size_t)b0 * HID;
    for (int idx = tid; idx < CHUNKB * HID; idx += NTHREADS) hf[idx] = sH[idx];
}

extern "C" void kernel_launch(void* const* d_in, const int* in_sizes, int n_in,
                              void* d_out, int out_size) {
    const float* x    = (const float*)d_in[0];
    const float* h0   = (const float*)d_in[1];
    const float* Wi0  = (const float*)d_in[2];
    const float* Wih  = (const float*)d_in[3];
    const float* Whh  = (const float*)d_in[4];
    const float* bih  = (const float*)d_in[5];
    const float* bhh  = (const float*)d_in[6];
    const float* Wout = (const float*)d_in[7];
    const float* bout = (const float*)d_in[8];
    float* out = (float*)d_out;

    cudaFuncSetAttribute(rnn_kernel, cudaFuncAttributeMaxDynamicSharedMemorySize,
                         SMEM_FLOATS * (int)sizeof(float));

    rnn_reset_kernel<<<1, 256>>>();
    rnn_kernel<<<NLAYERS * NCHUNK, NTHREADS, SMEM_FLOATS * sizeof(float)>>>(
        x, h0, Wi0, Wih, Whh, bih, bhh, Wout, bout, out);
}

// round 2
// speedup vs baseline: 1.1576x; 1.1576x over previous
#include <cuda_runtime.h>

#define NLAYERS 10
#define HID     100
#define HPAD    104
#define BATCH   512
#define TSTEPS  512
#define NCHUNK  16
#define CHUNKB  32
#define RING_D  8
#define NSTAGES 9          // stage0 = layers {0,1}; stage s>=1 = layer s+1
#define NTHREADS 256
#define NWARPS   8
#define JPW      13        // 8*13 = 104 >= 100

// ---- shared memory layout (floats) ----
#define OFF_W0   0                      // stage0: Whh[0];  stage s: Wih[s]
#define OFF_W1   (OFF_W0 + HPAD*HID)    // stage0: Wih[0];  stage s: Whh[s+1]
#define OFF_W2   (OFF_W1 + HPAD*HID)    // stage0 only: Whh[1]
#define OFF_BA   (OFF_W2 + HPAD*HID)    // stage0: bias L0; stage s: bias l
#define OFF_BB   (OFF_BA + HPAD)        // stage0: bias L1
#define OFF_AUX  (OFF_BB + HPAD)        // stage0: Wi0;  stage8: Wout
#define OFF_HA   (OFF_AUX + HPAD)       // [2][CHUNKB*HID] hidden (stage0: L0)
#define OFF_HB   (OFF_HA + 2*CHUNKB*HID)// stage0: [2] hidden L1; stage>=1: [0]=sInp
#define OFF_RED  (OFF_HB + 2*CHUNKB*HID)
#define OFF_SC   (OFF_RED + NWARPS*32)
#define SMEM_FLOATS (OFF_SC + 4)

// ---- global scratch: activation rings + flags ----
#define NPAIRS ((NSTAGES-1)*NCHUNK)     // 128
__device__ float    g_ring[(size_t)NPAIRS * RING_D * CHUNKB * HID];
__device__ unsigned g_prod[NPAIRS];
__device__ unsigned g_cons[NPAIRS];

__device__ __forceinline__ unsigned ld_acq(const unsigned* p) {
    unsigned v;
    asm volatile("ld.acquire.gpu.global.u32 %0, [%1];" : "=r"(v) : "l"(p) : "memory");
    return v;
}
__device__ __forceinline__ void st_rel(unsigned* p, unsigned v) {
    asm volatile("st.release.gpu.global.u32 [%0], %1;" :: "l"(p), "r"(v) : "memory");
}
__device__ __forceinline__ unsigned long long ffma2(unsigned long long a,
                                                    unsigned long long b,
                                                    unsigned long long c) {
    unsigned long long d;
    asm("fma.rn.f32x2 %0, %1, %2, %3;" : "=l"(d) : "l"(a), "l"(b), "l"(c));
    return d;
}
__device__ __forceinline__ unsigned long long pack2(float lo, float hi) {
    unsigned long long r;
    asm("mov.b64 %0, {%1, %2};" : "=l"(r) : "f"(lo), "f"(hi));
    return r;
}
__device__ __forceinline__ float hsum2(unsigned long long v) {
    float a, b;
    asm("mov.b64 {%0, %1}, %2;" : "=f"(a), "=f"(b) : "l"(v));
    return a + b;
}

__global__ void rnn_reset_kernel() {
    int i = threadIdx.x;
    if (i < NPAIRS) { g_prod[i] = 0u; g_cons[i] = 0u; }
}

// dual-matrix accumulate: tanh(bias + Wi*in + Wh*h) for 13 j's of this warp
__device__ __forceinline__ void mm_dual(const float* __restrict__ Wi,
                                        const float* __restrict__ Wh,
                                        const float* __restrict__ irow,
                                        const float* __restrict__ hrow,
                                        const float* __restrict__ bias,
                                        int jbase, float* hn) {
    unsigned long long acc[JPW];
#pragma unroll
    for (int i = 0; i < JPW; i++) acc[i] = pack2(bias[jbase + i], 0.f);
    for (int k = 0; k < HID; k += 4) {
        ulonglong2 in2 = *(const ulonglong2*)(irow + k);
        ulonglong2 h2  = *(const ulonglong2*)(hrow + k);
#pragma unroll
        for (int i = 0; i < JPW; i++) {
            ulonglong2 wi2 = *(const ulonglong2*)(Wi + (jbase + i) * HID + k);
            ulonglong2 wh2 = *(const ulonglong2*)(Wh + (jbase + i) * HID + k);
            acc[i] = ffma2(in2.x, wi2.x, acc[i]);
            acc[i] = ffma2(in2.y, wi2.y, acc[i]);
            acc[i] = ffma2(h2.x,  wh2.x, acc[i]);
            acc[i] = ffma2(h2.y,  wh2.y, acc[i]);
        }
    }
#pragma unroll
    for (int i = 0; i < JPW; i++) hn[i] = tanhf(hsum2(acc[i]));
}

// single-matrix (layer 0): tanh(bias + x*Wi0 + Wh*h)
__device__ __forceinline__ void mm_single(const float* __restrict__ Wh,
                                          const float* __restrict__ hrow,
                                          const float* __restrict__ bias,
                                          const float* __restrict__ aux,
                                          float xv, int jbase, float* hn) {
    unsigned long long acc[JPW];
#pragma unroll
    for (int i = 0; i < JPW; i++)
        acc[i] = pack2(bias[jbase + i] + xv * aux[jbase + i], 0.f);
    for (int k = 0; k < HID; k += 4) {
        ulonglong2 h2 = *(const ulonglong2*)(hrow + k);
#pragma unroll
        for (int i = 0; i < JPW; i++) {
            ulonglong2 wh2 = *(const ulonglong2*)(Wh + (jbase + i) * HID + k);
            acc[i] = ffma2(h2.x, wh2.x, acc[i]);
            acc[i] = ffma2(h2.y, wh2.y, acc[i]);
        }
    }
#pragma unroll
    for (int i = 0; i < JPW; i++) hn[i] = tanhf(hsum2(acc[i]));
}

__global__ __launch_bounds__(NTHREADS)
void rnn_kernel(const float* __restrict__ x,      // [B, T, 1]
                const float* __restrict__ h0,     // [L, B, H]
                const float* __restrict__ Wi0,    // [H, 1]
                const float* __restrict__ Wih,    // [L-1, H, H]
                const float* __restrict__ Whh,    // [L, H, H]
                const float* __restrict__ bih,    // [L, H]
                const float* __restrict__ bhh,    // [L, H]
                const float* __restrict__ Wout,   // [1, H]
                const float* __restrict__ bout,   // [1]
                float* __restrict__ out)          // [B*T] outs ++ [L*B*H] h_final
{
    extern __shared__ float sm[];
    float* sW0   = sm + OFF_W0;
    float* sW1   = sm + OFF_W1;
    float* sW2   = sm + OFF_W2;
    float* sBA   = sm + OFF_BA;
    float* sBB   = sm + OFF_BB;
    float* sAux  = sm + OFF_AUX;
    float* sHA   = sm + OFF_HA;   // [2][CHUNKB*HID]
    float* sHB   = sm + OFF_HB;   // [2][CHUNKB*HID] (stage>=1: [0] is sInp)
    float* sRed  = sm + OFF_RED;
    float* sSC   = sm + OFF_SC;

    const int tid   = threadIdx.x;
    const int warp  = tid >> 5;
    const int lane  = tid & 31;
    const int stage = blockIdx.x / NCHUNK;
    const int chunk = blockIdx.x % NCHUNK;
    const int b0    = chunk * CHUNKB;
    const int jbase = warp * JPW;

    // ---------------- init smem ----------------
    {
        if (stage == 0) {
            const float* gW0 = Whh;                         // layer 0 Whh
            const float* gW1 = Wih;                         // layer 1 Wih (= Wih[0])
            const float* gW2 = Whh + (size_t)HID * HID;     // layer 1 Whh
            for (int idx = tid; idx < HPAD * HID; idx += NTHREADS) {
                int j = idx / HID;
                bool v = j < HID;
                sW0[idx] = v ? gW0[idx] : 0.f;
                sW1[idx] = v ? gW1[idx] : 0.f;
                sW2[idx] = v ? gW2[idx] : 0.f;
            }
            for (int idx = tid; idx < HPAD; idx += NTHREADS) {
                bool v = idx < HID;
                sBA[idx]  = v ? (bih[idx] + bhh[idx]) : 0.f;
                sBB[idx]  = v ? (bih[HID + idx] + bhh[HID + idx]) : 0.f;
                sAux[idx] = v ? Wi0[idx] : 0.f;
            }
            const float* gh0 = h0 + (size_t)b0 * HID;                       // layer 0
            const float* gh1 = h0 + (size_t)BATCH * HID + (size_t)b0 * HID; // layer 1
            for (int idx = tid; idx < CHUNKB * HID; idx += NTHREADS) {
                sHA[idx] = gh0[idx];
                sHB[idx] = gh1[idx];
            }
        } else {
            const int l = stage + 1;
            const float* gW0 = Wih + (size_t)(l - 1) * HID * HID;
            const float* gW1 = Whh + (size_t)l * HID * HID;
            for (int idx = tid; idx < HPAD * HID; idx += NTHREADS) {
                int j = idx / HID;
                bool v = j < HID;
                sW0[idx] = v ? gW0[idx] : 0.f;
                sW1[idx] = v ? gW1[idx] : 0.f;
            }
            for (int idx = tid; idx < HPAD; idx += NTHREADS) {
                bool v = idx < HID;
                sBA[idx]  = v ? (bih[l * HID + idx] + bhh[l * HID + idx]) : 0.f;
                sAux[idx] = (v && stage == NSTAGES - 1) ? Wout[idx] : 0.f;
            }
            const float* gh = h0 + (size_t)l * BATCH * HID + (size_t)b0 * HID;
            for (int idx = tid; idx < CHUNKB * HID; idx += NTHREADS) sHA[idx] = gh[idx];
        }
        if (tid == 0) sSC[0] = bout[0];
    }
    __syncthreads();

    const int pc_in  = (stage - 1) * NCHUNK + chunk;  // valid stage>=1
    const int pc_out = stage * NCHUNK + chunk;        // valid stage<8
    float* ring_in  = g_ring + (size_t)pc_in  * RING_D * CHUNKB * HID;
    float* ring_out = g_ring + (size_t)pc_out * RING_D * CHUNKB * HID;

    float hn[JPW];

    if (stage == 0) {
        float xv = x[(size_t)(b0 + lane) * TSTEPS];  // t=0 prefetched
        for (int t = 0; t < TSTEPS; t++) {
            const int cur = t & 1, nxt = cur ^ 1;
            float* hA_cur = sHA + cur * CHUNKB * HID;
            float* hA_nxt = sHA + nxt * CHUNKB * HID;
            float* hB_cur = sHB + cur * CHUNKB * HID;
            float* hB_nxt = sHB + nxt * CHUNKB * HID;

            // ---- layer 0 ----
            mm_single(sW0, hA_cur + lane * HID, sBA, sAux, xv, jbase, hn);
            if (t + 1 < TSTEPS) xv = x[(size_t)(b0 + lane) * TSTEPS + t + 1];
#pragma unroll
            for (int i = 0; i < JPW; i++) {
                int j = jbase + i;
                if (j < HID) hA_nxt[lane * HID + j] = hn[i];
            }
            if (tid == 0 && t >= RING_D) {
                unsigned need = (unsigned)(t + 1 - RING_D);
                while (ld_acq(&g_cons[pc_out]) < need) {}
            }
            __syncthreads();  // hA_nxt ready for layer 1; backpressure confirmed

            // ---- layer 1 ----
            mm_dual(sW1, sW2, hA_nxt + lane * HID, hB_cur + lane * HID, sBB, jbase, hn);
            float* slot = ring_out + (size_t)(t & (RING_D - 1)) * CHUNKB * HID;
#pragma unroll
            for (int i = 0; i < JPW; i++) {
                int j = jbase + i;
                if (j < HID) { hB_nxt[lane * HID + j] = hn[i]; slot[lane * HID + j] = hn[i]; }
            }
            __syncthreads();  // slot writes complete
            if (tid == 0) st_rel(&g_prod[pc_out], (unsigned)(t + 1));
        }
        // final hidden: layers 0 and 1 (buffer parity 512&1 = 0)
        float* hf0 = out + (size_t)BATCH * TSTEPS + (size_t)b0 * HID;
        float* hf1 = out + (size_t)BATCH * TSTEPS + (size_t)BATCH * HID + (size_t)b0 * HID;
        for (int idx = tid; idx < CHUNKB * HID; idx += NTHREADS) {
            hf0[idx] = sHA[idx];
            hf1[idx] = sHB[idx];
        }
    } else {
        const bool last = (stage == NSTAGES - 1);
        float* sInp = sHB;  // single buffer
        for (int t = 0; t < TSTEPS; t++) {
            const int cur = t & 1, nxt = cur ^ 1;
            float* hA_cur = sHA + cur * CHUNKB * HID;
            float* hA_nxt = sHA + nxt * CHUNKB * HID;

            if (tid == 0) {
                while (ld_acq(&g_prod[pc_in]) < (unsigned)(t + 1)) {}
                if (!last && t >= RING_D) {
                    unsigned need = (unsigned)(t + 1 - RING_D);
                    while (ld_acq(&g_cons[pc_out]) < need) {}
                }
            }
            __syncthreads();  // b1: input available, backpressure ok

            const float4* src = (const float4*)(ring_in + (size_t)(t & (RING_D - 1)) * CHUNKB * HID);
            float4* dst = (float4*)sInp;
#pragma unroll
            for (int i = tid; i < CHUNKB * HID / 4; i += NTHREADS) dst[i] = __ldcg(src + i);
            __syncthreads();  // b2: input staged
            if (tid == 0) st_rel(&g_cons[pc_in], (unsigned)(t + 1));

            mm_dual(sW0, sW1, sInp + lane * HID, hA_cur + lane * HID, sBA, jbase, hn);

            if (!last) {
                float* slot = ring_out + (size_t)(t & (RING_D - 1)) * CHUNKB * HID;
#pragma unroll
                for (int i = 0; i < JPW; i++) {
                    int j = jbase + i;
                    if (j < HID) { hA_nxt[lane * HID + j] = hn[i]; slot[lane * HID + j] = hn[i]; }
                }
                __syncthreads();  // b3
                if (tid == 0) st_rel(&g_prod[pc_out], (unsigned)(t + 1));
            } else {
                float part = 0.f;
#pragma unroll
                for (int i = 0; i < JPW; i++) {
                    int j = jbase + i;
                    if (j < HID) { hA_nxt[lane * HID + j] = hn[i]; part += hn[i] * sAux[j]; }
                }
                sRed[warp * 32 + lane] = part;
                __syncthreads();  // b3
                if (warp == 0) {
                    float s = sSC[0];
#pragma unroll
                    for (int w = 0; w < NWARPS; w++) s += sRed[w * 32 + lane];
                    out[(size_t)(b0 + lane) * TSTEPS + t] = s;
                }
            }
        }
        const int l = stage + 1;
        float* hf = out + (size_t)BATCH * TSTEPS + (size_t)l * BATCH * HID + (size_t)b0 * HID;
        __syncthreads();
        for (int idx = tid; idx < CHUNKB * HID; idx += NTHREADS) hf[idx] = sHA[idx];
    }
}

extern "C" void kernel_launch(void* const* d_in, const int* in_sizes, int n_in,
                              void* d_out, int out_size) {
    const float* x    = (const float*)d_in[0];
    const float* h0   = (const float*)d_in[1];
    const float* Wi0  = (const float*)d_in[2];
    const float* Wih  = (const float*)d_in[3];
    const float* Whh  = (const float*)d_in[4];
    const float* bih  = (const float*)d_in[5];
    const float* bhh  = (const float*)d_in[6];
    const float* Wout = (const float*)d_in[7];
    const float* bout = (const float*)d_in[8];
    float* out = (float*)d_out;

    cudaFuncSetAttribute(rnn_kernel, cudaFuncAttributeMaxDynamicSharedMemorySize,
                         SMEM_FLOATS * (int)sizeof(float));

    rnn_reset_kernel<<<1, 256>>>();
    rnn_kernel<<<NSTAGES * NCHUNK, NTHREADS, SMEM_FLOATS * sizeof(float)>>>(
        x, h0, Wi0, Wih, Whh, bih, bhh, Wout, bout, out);
}

// round 3
// speedup vs baseline: 1.2191x; 1.0531x over previous
#include <cuda_runtime.h>

#define NLAYERS 10
#define HID     100
#define HPAD    104
#define BATCH   512
#define TSTEPS  512
#define NCHUNK  16
#define CHUNKB  32
#define RING_D  8
#define NSTAGES 9          // stage0 = layers {0,1}; stage s>=1 = layer s+1
#define NTHREADS 256
#define NWARPS   8
#define JPW      13        // 8*13 = 104 >= 100

// ---- shared memory layout (floats) ----
#define OFF_W0   0                      // stage0: Whh[0];  stage s: Wih[s]
#define OFF_W1   (OFF_W0 + HPAD*HID)    // stage0: Wih[0];  stage s: Whh[s+1]
#define OFF_W2   (OFF_W1 + HPAD*HID)    // stage0 only: Whh[1]
#define OFF_BA   (OFF_W2 + HPAD*HID)    // stage0: bias L0; stage s: bias l
#define OFF_BB   (OFF_BA + HPAD)        // stage0: bias L1
#define OFF_AUX  (OFF_BB + HPAD)        // stage0: Wi0;  stage8: Wout
#define OFF_HA   (OFF_AUX + HPAD)       // [2][CHUNKB*HID] hidden (stage0: L0)
#define OFF_HB   (OFF_HA + 2*CHUNKB*HID)// stage0: [2] hidden L1; stage>=1: [0]=sInp
#define OFF_RED  (OFF_HB + 2*CHUNKB*HID)
#define OFF_SC   (OFF_RED + NWARPS*32)
#define SMEM_FLOATS (OFF_SC + 4)

// ---- global scratch: activation rings + flags ----
#define NPAIRS ((NSTAGES-1)*NCHUNK)     // 128
__device__ float    g_ring[(size_t)NPAIRS * RING_D * CHUNKB * HID];
__device__ unsigned g_prod[NPAIRS];
__device__ unsigned g_cons[NPAIRS];

__device__ __forceinline__ unsigned ld_acq(const unsigned* p) {
    unsigned v;
    asm volatile("ld.acquire.gpu.global.u32 %0, [%1];" : "=r"(v) : "l"(p) : "memory");
    return v;
}
__device__ __forceinline__ void st_rel(unsigned* p, unsigned v) {
    asm volatile("st.release.gpu.global.u32 [%0], %1;" :: "l"(p), "r"(v) : "memory");
}
__device__ __forceinline__ unsigned long long ffma2(unsigned long long a,
                                                    unsigned long long b,
                                                    unsigned long long c) {
    unsigned long long d;
    asm("fma.rn.f32x2 %0, %1, %2, %3;" : "=l"(d) : "l"(a), "l"(b), "l"(c));
    return d;
}
__device__ __forceinline__ unsigned long long pack2(float lo, float hi) {
    unsigned long long r;
    asm("mov.b64 %0, {%1, %2};" : "=l"(r) : "f"(lo), "f"(hi));
    return r;
}
__device__ __forceinline__ float hsum2(unsigned long long v) {
    float a, b;
    asm("mov.b64 {%0, %1}, %2;" : "=f"(a), "=f"(b) : "l"(v));
    return a + b;
}

__global__ void rnn_reset_kernel() {
    int i = threadIdx.x;
    if (i < NPAIRS) { g_prod[i] = 0u; g_cons[i] = 0u; }
}

// dual-matrix accumulate: tanh(bias + Wi*in + Wh*h) for 13 j's of this warp
__device__ __forceinline__ void mm_dual(const float* __restrict__ Wi,
                                        const float* __restrict__ Wh,
                                        const float* __restrict__ irow,
                                        const float* __restrict__ hrow,
                                        const float* __restrict__ bias,
                                        int jbase, float* hn) {
    unsigned long long acc[JPW];
#pragma unroll
    for (int i = 0; i < JPW; i++) acc[i] = pack2(bias[jbase + i], 0.f);
    for (int k = 0; k < HID; k += 4) {
        ulonglong2 in2 = *(const ulonglong2*)(irow + k);
        ulonglong2 h2  = *(const ulonglong2*)(hrow + k);
#pragma unroll
        for (int i = 0; i < JPW; i++) {
            ulonglong2 wi2 = *(const ulonglong2*)(Wi + (jbase + i) * HID + k);
            ulonglong2 wh2 = *(const ulonglong2*)(Wh + (jbase + i) * HID + k);
            acc[i] = ffma2(in2.x, wi2.x, acc[i]);
            acc[i] = ffma2(in2.y, wi2.y, acc[i]);
            acc[i] = ffma2(h2.x,  wh2.x, acc[i]);
            acc[i] = ffma2(h2.y,  wh2.y, acc[i]);
        }
    }
#pragma unroll
    for (int i = 0; i < JPW; i++) hn[i] = tanhf(hsum2(acc[i]));
}

// single-matrix (layer 0): tanh(bias + x*Wi0 + Wh*h)
__device__ __forceinline__ void mm_single(const float* __restrict__ Wh,
                                          const float* __restrict__ hrow,
                                          const float* __restrict__ bias,
                                          const float* __restrict__ aux,
                                          float xv, int jbase, float* hn) {
    unsigned long long acc[JPW];
#pragma unroll
    for (int i = 0; i < JPW; i++)
        acc[i] = pack2(bias[jbase + i] + xv * aux[jbase + i], 0.f);
    for (int k = 0; k < HID; k += 4) {
        ulonglong2 h2 = *(const ulonglong2*)(hrow + k);
#pragma unroll
        for (int i = 0; i < JPW; i++) {
            ulonglong2 wh2 = *(const ulonglong2*)(Wh + (jbase + i) * HID + k);
            acc[i] = ffma2(h2.x, wh2.x, acc[i]);
            acc[i] = ffma2(h2.y, wh2.y, acc[i]);
        }
    }
#pragma unroll
    for (int i = 0; i < JPW; i++) hn[i] = tanhf(hsum2(acc[i]));
}

__global__ __launch_bounds__(NTHREADS)
void rnn_kernel(const float* __restrict__ x,      // [B, T, 1]
                const float* __restrict__ h0,     // [L, B, H]
                const float* __restrict__ Wi0,    // [H, 1]
                const float* __restrict__ Wih,    // [L-1, H, H]
                const float* __restrict__ Whh,    // [L, H, H]
                const float* __restrict__ bih,    // [L, H]
                const float* __restrict__ bhh,    // [L, H]
                const float* __restrict__ Wout,   // [1, H]
                const float* __restrict__ bout,   // [1]
                float* __restrict__ out)          // [B*T] outs ++ [L*B*H] h_final
{
    extern __shared__ float sm[];
    float* sW0   = sm + OFF_W0;
    float* sW1   = sm + OFF_W1;
    float* sW2   = sm + OFF_W2;
    float* sBA   = sm + OFF_BA;
    float* sBB   = sm + OFF_BB;
    float* sAux  = sm + OFF_AUX;
    float* sHA   = sm + OFF_HA;   // [2][CHUNKB*HID]
    float* sHB   = sm + OFF_HB;   // [2][CHUNKB*HID] (stage>=1: [0] is sInp)
    float* sRed  = sm + OFF_RED;
    float* sSC   = sm + OFF_SC;

    const int tid   = threadIdx.x;
    const int warp  = tid >> 5;
    const int lane  = tid & 31;
    const int stage = blockIdx.x / NCHUNK;
    const int chunk = blockIdx.x % NCHUNK;
    const int b0    = chunk * CHUNKB;
    const int jbase = warp * JPW;

    // ---------------- init smem ----------------
    {
        if (stage == 0) {
            const float* gW0 = Whh;                         // layer 0 Whh
            const float* gW1 = Wih;                         // layer 1 Wih (= Wih[0])
            const float* gW2 = Whh + (size_t)HID * HID;     // layer 1 Whh
            for (int idx = tid; idx < HPAD * HID; idx += NTHREADS) {
                int j = idx / HID;
                bool v = j < HID;
                sW0[idx] = v ? gW0[idx] : 0.f;
                sW1[idx] = v ? gW1[idx] : 0.f;
                sW2[idx] = v ? gW2[idx] : 0.f;
            }
            for (int idx = tid; idx < HPAD; idx += NTHREADS) {
                bool v = idx < HID;
                sBA[idx]  = v ? (bih[idx] + bhh[idx]) : 0.f;
                sBB[idx]  = v ? (bih[HID + idx] + bhh[HID + idx]) : 0.f;
                sAux[idx] = v ? Wi0[idx] : 0.f;
            }
            const float* gh0 = h0 + (size_t)b0 * HID;                       // layer 0
            const float* gh1 = h0 + (size_t)BATCH * HID + (size_t)b0 * HID; // layer 1
            for (int idx = tid; idx < CHUNKB * HID; idx += NTHREADS) {
                sHA[idx] = gh0[idx];
                sHB[idx] = gh1[idx];
            }
        } else {
            const int l = stage + 1;
            const float* gW0 = Wih + (size_t)(l - 1) * HID * HID;
            const float* gW1 = Whh + (size_t)l * HID * HID;
            for (int idx = tid; idx < HPAD * HID; idx += NTHREADS) {
                int j = idx / HID;
                bool v = j < HID;
                sW0[idx] = v ? gW0[idx] : 0.f;
                sW1[idx] = v ? gW1[idx] : 0.f;
            }
            for (int idx = tid; idx < HPAD; idx += NTHREADS) {
                bool v = idx < HID;
                sBA[idx]  = v ? (bih[l * HID + idx] + bhh[l * HID + idx]) : 0.f;
                sAux[idx] = (v && stage == NSTAGES - 1) ? Wout[idx] : 0.f;
            }
            const float* gh = h0 + (size_t)l * BATCH * HID + (size_t)b0 * HID;
            for (int idx = tid; idx < CHUNKB * HID; idx += NTHREADS) sHA[idx] = gh[idx];
        }
        if (tid == 0) sSC[0] = bout[0];
    }
    __syncthreads();

    const int pc_in  = (stage - 1) * NCHUNK + chunk;  // valid stage>=1
    const int pc_out = stage * NCHUNK + chunk;        // valid stage<8
    float* ring_in  = g_ring + (size_t)pc_in  * RING_D * CHUNKB * HID;
    float* ring_out = g_ring + (size_t)pc_out * RING_D * CHUNKB * HID;

    float hn[JPW];

    if (stage == 0) {
        float xv = x[(size_t)(b0 + lane) * TSTEPS];  // t=0 prefetched
        for (int t = 0; t < TSTEPS; t++) {
            const int cur = t & 1, nxt = cur ^ 1;
            float* hA_cur = sHA + cur * CHUNKB * HID;
            float* hA_nxt = sHA + nxt * CHUNKB * HID;
            float* hB_cur = sHB + cur * CHUNKB * HID;
            float* hB_nxt = sHB + nxt * CHUNKB * HID;

            // ---- layer 0 ----
            mm_single(sW0, hA_cur + lane * HID, sBA, sAux, xv, jbase, hn);
            if (t + 1 < TSTEPS) xv = x[(size_t)(b0 + lane) * TSTEPS + t + 1];
#pragma unroll
            for (int i = 0; i < JPW; i++) {
                int j = jbase + i;
                if (j < HID) hA_nxt[lane * HID + j] = hn[i];
            }
            if (tid == 0 && t >= RING_D) {
                unsigned need = (unsigned)(t + 1 - RING_D);
                while (ld_acq(&g_cons[pc_out]) < need) {}
            }
            __syncthreads();  // hA_nxt ready for layer 1; backpressure confirmed

            // ---- layer 1 ----
            mm_dual(sW1, sW2, hA_nxt + lane * HID, hB_cur + lane * HID, sBB, jbase, hn);
            float* slot = ring_out + (size_t)(t & (RING_D - 1)) * CHUNKB * HID;
#pragma unroll
            for (int i = 0; i < JPW; i++) {
                int j = jbase + i;
                if (j < HID) { hB_nxt[lane * HID + j] = hn[i]; slot[lane * HID + j] = hn[i]; }
            }
            __syncthreads();  // slot writes complete
            if (tid == 0) st_rel(&g_prod[pc_out], (unsigned)(t + 1));
        }
        // final hidden: layers 0 and 1 (buffer parity 512&1 = 0)
        float* hf0 = out + (size_t)BATCH * TSTEPS + (size_t)b0 * HID;
        float* hf1 = out + (size_t)BATCH * TSTEPS + (size_t)BATCH * HID + (size_t)b0 * HID;
        for (int idx = tid; idx < CHUNKB * HID; idx += NTHREADS) {
            hf0[idx] = sHA[idx];
            hf1[idx] = sHB[idx];
        }
    } else {
        const bool last = (stage == NSTAGES - 1);
        float* sInp = sHB;  // single buffer
        for (int t = 0; t < TSTEPS; t++) {
            const int cur = t & 1, nxt = cur ^ 1;
            float* hA_cur = sHA + cur * CHUNKB * HID;
            float* hA_nxt = sHA + nxt * CHUNKB * HID;

            if (tid == 0) {
                while (ld_acq(&g_prod[pc_in]) < (unsigned)(t + 1)) {}
                if (!last && t >= RING_D) {
                    unsigned need = (unsigned)(t + 1 - RING_D);
                    while (ld_acq(&g_cons[pc_out]) < need) {}
                }
            }
            __syncthreads();  // b1: input available, backpressure ok

            const float4* src = (const float4*)(ring_in + (size_t)(t & (RING_D - 1)) * CHUNKB * HID);
            float4* dst = (float4*)sInp;
#pragma unroll
            for (int i = tid; i < CHUNKB * HID / 4; i += NTHREADS) dst[i] = __ldcg(src + i);
            __syncthreads();  // b2: input staged
            if (tid == 0) st_rel(&g_cons[pc_in], (unsigned)(t + 1));

            mm_dual(sW0, sW1, sInp + lane * HID, hA_cur + lane * HID, sBA, jbase, hn);

            if (!last) {
                float* slot = ring_out + (size_t)(t & (RING_D - 1)) * CHUNKB * HID;
#pragma unroll
                for (int i = 0; i < JPW; i++) {
                    int j = jbase + i;
                    if (j < HID) { hA_nxt[lane * HID + j] = hn[i]; slot[lane * HID + j] = hn[i]; }
                }
                __syncthreads();  // b3
                if (tid == 0) st_rel(&g_prod[pc_out], (unsigned)(t + 1));
            } else {
                float part = 0.f;
#pragma unroll
                for (int i = 0; i < JPW; i++) {
                    int j = jbase + i;
                    if (j < HID) { hA_nxt[lane * HID + j] = hn[i]; part += hn[i] * sAux[j]; }
                }
                sRed[warp * 32 + lane] = part;
                __syncthreads();  // b3
                if (warp == 0) {
                    float s = sSC[0];
#pragma unroll
                    for (int w = 0; w < NWARPS; w++) s += sRed[w * 32 + lane];
                    out[(size_t)(b0 + lane) * TSTEPS + t] = s;
                }
            }
        }
        const int l = stage + 1;
        float* hf = out + (size_t)BATCH * TSTEPS + (size_t)l * BATCH * HID + (size_t)b0 * HID;
        __syncthreads();
        for (int idx = tid; idx < CHUNKB * HID; idx += NTHREADS) hf[idx] = sHA[idx];
    }
}

extern "C" void kernel_launch(void* const* d_in, const int* in_sizes, int n_in,
                              void* d_out, int out_size) {
    const float* x    = (const float*)d_in[0];
    const float* h0   = (const float*)d_in[1];
    const float* Wi0  = (const float*)d_in[2];
    const float* Wih  = (const float*)d_in[3];
    const float* Whh  = (const float*)d_in[4];
    const float* bih  = (const float*)d_in[5];
    const float* bhh  = (const float*)d_in[6];
    const float* Wout = (const float*)d_in[7];
    const float* bout = (const float*)d_in[8];
    float* out = (float*)d_out;

    cudaFuncSetAttribute(rnn_kernel, cudaFuncAttributeMaxDynamicSharedMemorySize,
                         SMEM_FLOATS * (int)sizeof(float));

    rnn_reset_kernel<<<1, 256>>>();
    rnn_kernel<<<NSTAGES * NCHUNK, NTHREADS, SMEM_FLOATS * sizeof(float)>>>(
        x, h0, Wi0, Wih, Whh, bih, bhh, Wout, bout, out);
}